// round 3
// baseline (speedup 1.0000x reference)
#include <cuda_runtime.h>
#include <cuda_bf16.h>

// Fused GraphSAGE layer:
//   agg[n]  = (sum_s features[neigh[n,s]] + features[node[n]]) / (S+1)
//   out[n]  = l2norm(relu(agg[n] @ W + b))
//
// One block = 32 nodes, 512 threads.
// Phase 1: float4 gather, 4 node accumulators/thread; agg stored DUPLICATED
//          in smem as float2 (a,a) so f32x2 FMA operands need no packing.
// Phase 2: fp32x2 packed-FMA GEMM (4 rows x 4 cols per thread -> 16 f32x2 acc).
// Phase 3: bias/relu/l2norm epilogue fused.

#define BM      32
#define DDIM    256
#define THREADS 512
#define MAX_S   40

// smem layout (dynamic): Asd float2[BM][DDIM] (64KB) | idxS int[BM*MAX_S] | invN float[BM]
#define ASD_BYTES   (BM * DDIM * 8)
#define IDX_BYTES   (BM * MAX_S * 4)
#define SMEM_BYTES  (ASD_BYTES + IDX_BYTES + BM * 4)

__device__ __forceinline__ void fma2(unsigned long long& d,
                                     unsigned long long a,
                                     unsigned long long b)
{
    asm("fma.rn.f32x2 %0, %1, %2, %0;" : "+l"(d) : "l"(a), "l"(b));
}

__device__ __forceinline__ float lo32(unsigned long long v)
{ return __int_as_float((int)(v & 0xffffffffULL)); }
__device__ __forceinline__ float hi32(unsigned long long v)
{ return __int_as_float((int)(v >> 32)); }

__global__ __launch_bounds__(THREADS, 2)
void gsage_fused_kernel(const int*   __restrict__ node_idx,
                        const int*   __restrict__ neigh_idx,
                        const float* __restrict__ features,
                        const float* __restrict__ W,
                        const float* __restrict__ b,
                        float*       __restrict__ out,
                        int n_nodes, int n_samp)
{
    extern __shared__ char smem[];
    float2 (*Asd)[DDIM] = reinterpret_cast<float2(*)[DDIM]>(smem);
    int*   idxS = reinterpret_cast<int*>(smem + ASD_BYTES);
    float* invN = reinterpret_cast<float*>(smem + ASD_BYTES + IDX_BYTES);

    const int tid       = threadIdx.x;
    const int blockBase = blockIdx.x * BM;
    const int rows      = min(BM, n_nodes - blockBase);
    const int S         = n_samp + 1;

    // ---- stage indices: slot 0 = self, slots 1..n_samp = neighbors ----
    for (int i = tid; i < rows * S; i += THREADS) {
        int n = i / S, s = i - n * S;
        int gn = blockBase + n;
        idxS[n * S + s] = (s == 0) ? node_idx[gn]
                                   : neigh_idx[(long)gn * n_samp + (s - 1)];
    }
    __syncthreads();

    // ---- gather + mean: float4 columns, 4 nodes per thread, duplicated store ----
    {
        const int c4  = tid & 63;     // float4 column 0..63 (k = 4*c4..4*c4+3)
        const int n0  = (tid >> 6) * 4;
        const float4* F4 = reinterpret_cast<const float4*>(features);

        const bool v0 = (n0 + 0) < rows;
        const bool v1 = (n0 + 1) < rows;
        const bool v2 = (n0 + 2) < rows;
        const bool v3 = (n0 + 3) < rows;
        const int* ip0 = idxS + (v0 ? (n0 + 0) * S : 0);
        const int* ip1 = idxS + (v1 ? (n0 + 1) * S : 0);
        const int* ip2 = idxS + (v2 ? (n0 + 2) * S : 0);
        const int* ip3 = idxS + (v3 ? (n0 + 3) * S : 0);

        float4 a0 = {0,0,0,0}, a1 = {0,0,0,0}, a2 = {0,0,0,0}, a3 = {0,0,0,0};

        #pragma unroll 2
        for (int s = 0; s < S; ++s) {
            float4 t0 = __ldg(F4 + (long)ip0[s] * (DDIM/4) + c4);
            float4 t1 = __ldg(F4 + (long)ip1[s] * (DDIM/4) + c4);
            float4 t2 = __ldg(F4 + (long)ip2[s] * (DDIM/4) + c4);
            float4 t3 = __ldg(F4 + (long)ip3[s] * (DDIM/4) + c4);
            a0.x += t0.x; a0.y += t0.y; a0.z += t0.z; a0.w += t0.w;
            a1.x += t1.x; a1.y += t1.y; a1.z += t1.z; a1.w += t1.w;
            a2.x += t2.x; a2.y += t2.y; a2.z += t2.z; a2.w += t2.w;
            a3.x += t3.x; a3.y += t3.y; a3.z += t3.z; a3.w += t3.w;
        }

        const float invS = 1.0f / (float)S;
        const float m0 = v0 ? invS : 0.0f, m1 = v1 ? invS : 0.0f;
        const float m2 = v2 ? invS : 0.0f, m3 = v3 ? invS : 0.0f;
        a0.x *= m0; a0.y *= m0; a0.z *= m0; a0.w *= m0;
        a1.x *= m1; a1.y *= m1; a1.z *= m1; a1.w *= m1;
        a2.x *= m2; a2.y *= m2; a2.z *= m2; a2.w *= m2;
        a3.x *= m3; a3.y *= m3; a3.z *= m3; a3.w *= m3;

        // duplicated store: Asd[n][k] = (a,a)
        float4* d0 = reinterpret_cast<float4*>(&Asd[n0 + 0][4 * c4]);
        float4* d1 = reinterpret_cast<float4*>(&Asd[n0 + 1][4 * c4]);
        float4* d2 = reinterpret_cast<float4*>(&Asd[n0 + 2][4 * c4]);
        float4* d3 = reinterpret_cast<float4*>(&Asd[n0 + 3][4 * c4]);
        d0[0] = make_float4(a0.x, a0.x, a0.y, a0.y);
        d0[1] = make_float4(a0.z, a0.z, a0.w, a0.w);
        d1[0] = make_float4(a1.x, a1.x, a1.y, a1.y);
        d1[1] = make_float4(a1.z, a1.z, a1.w, a1.w);
        d2[0] = make_float4(a2.x, a2.x, a2.y, a2.y);
        d2[1] = make_float4(a2.z, a2.z, a2.w, a2.w);
        d3[0] = make_float4(a3.x, a3.x, a3.y, a3.y);
        d3[1] = make_float4(a3.z, a3.z, a3.w, a3.w);
    }
    __syncthreads();

    // ---- f32x2 register-tiled GEMM: 4 rows x 4 cols (2 col-pairs) / thread ----
    const int ct = tid & 63;          // cols 4*ct .. 4*ct+3
    const int rowBase = (tid >> 6) * 4;

    unsigned long long acc[4][2];
    #pragma unroll
    for (int r = 0; r < 4; ++r) { acc[r][0] = 0ULL; acc[r][1] = 0ULL; }

    const float* Wcol = W + 4 * ct;   // column offset

    #pragma unroll 4
    for (int k = 0; k < DDIM; k += 2) {
        // W pairs for k and k+1: each 16B load = 2 ready f32x2 operands
        ulonglong2 w0 = *reinterpret_cast<const ulonglong2*>(Wcol + (k + 0) * DDIM);
        ulonglong2 w1 = *reinterpret_cast<const ulonglong2*>(Wcol + (k + 1) * DDIM);

        #pragma unroll
        for (int r = 0; r < 4; ++r) {
            // (a_k,a_k,a_k1,a_k1) via one LDS.128 broadcast
            ulonglong2 ap = *reinterpret_cast<const ulonglong2*>(&Asd[rowBase + r][k]);
            fma2(acc[r][0], ap.x, w0.x);
            fma2(acc[r][1], ap.x, w0.y);
            fma2(acc[r][0], ap.y, w1.x);
            fma2(acc[r][1], ap.y, w1.y);
        }
    }

    // ---- epilogue: bias + relu, stash into smem (reuse Asd region as float tile) ----
    float* Os = reinterpret_cast<float*>(smem);   // [BM][DDIM] floats (32KB)
    const float4 bias = __ldg(&reinterpret_cast<const float4*>(b)[ct]);
    __syncthreads();   // all A reads done before overwrite
    #pragma unroll
    for (int r = 0; r < 4; ++r) {
        float4 v;
        v.x = fmaxf(lo32(acc[r][0]) + bias.x, 0.0f);
        v.y = fmaxf(hi32(acc[r][0]) + bias.y, 0.0f);
        v.z = fmaxf(lo32(acc[r][1]) + bias.z, 0.0f);
        v.w = fmaxf(hi32(acc[r][1]) + bias.w, 0.0f);
        reinterpret_cast<float4*>(&Os[(rowBase + r) * DDIM])[ct] = v;
    }
    __syncthreads();

    // ---- per-row L2 norm: warp w handles rows 2w, 2w+1 ----
    const int wid = tid >> 5, lane = tid & 31;
    #pragma unroll
    for (int rr = 0; rr < 2; ++rr) {
        int row = wid * 2 + rr;
        float s = 0.0f;
        #pragma unroll
        for (int j = 0; j < 8; ++j) {
            float v = Os[row * DDIM + lane + 32 * j];
            s = fmaf(v, v, s);
        }
        #pragma unroll
        for (int o = 16; o > 0; o >>= 1)
            s += __shfl_xor_sync(0xffffffffu, s, o);
        if (lane == 0)
            invN[row] = 1.0f / fmaxf(sqrtf(s), 1e-12f);
    }
    __syncthreads();

    // ---- normalized vectorized store ----
    float4* out4 = reinterpret_cast<float4*>(out);
    const float4* Os4 = reinterpret_cast<const float4*>(Os);
    for (int i = tid; i < BM * (DDIM / 4); i += THREADS) {
        int r = i >> 6;
        if (r < rows) {
            float4 v = Os4[i];
            float sc = invN[r];
            v.x *= sc; v.y *= sc; v.z *= sc; v.w *= sc;
            out4[(long)(blockBase + r) * (DDIM / 4) + (i & 63)] = v;
        }
    }
}

extern "C" void kernel_launch(void* const* d_in, const int* in_sizes, int n_in,
                              void* d_out, int out_size)
{
    const int*   node_idx  = (const int*)  d_in[0];
    const int*   neigh_idx = (const int*)  d_in[1];
    const float* features  = (const float*)d_in[2];
    const float* W         = (const float*)d_in[3];
    const float* b         = (const float*)d_in[4];
    float*       out       = (float*)      d_out;

    const int n_nodes = in_sizes[0];
    const int n_samp  = in_sizes[1] / n_nodes;   // 32

    cudaFuncSetAttribute(gsage_fused_kernel,
                         cudaFuncAttributeMaxDynamicSharedMemorySize, SMEM_BYTES);

    const int grid = (n_nodes + BM - 1) / BM;
    gsage_fused_kernel<<<grid, THREADS, SMEM_BYTES>>>(node_idx, neigh_idx,
                                                      features, W, b, out,
                                                      n_nodes, n_samp);
}